// round 2
// baseline (speedup 1.0000x reference)
#include <cuda_runtime.h>

// Problem dims (fixed by the reference)
#define BB 8
#define CC 256
#define NN 2048

// Scratch (no allocations allowed -> __device__ globals)
__device__ float g_q[BB * CC * NN];     // 16 MB
__device__ float g_k[BB * CC * NN];     // 16 MB
__device__ float g_v[BB * CC * NN];     // 16 MB
__device__ float g_M[BB * CC * CC];     // 2 MB   M[b] = V_b @ Q_b^T
__device__ float g_partial[BB * CC];    // per-(b,c) qsum*ksum
__device__ float g_inv;                 // 1/S

// ---------------------------------------------------------------------------
// Kernel 1: q/k/v = W @ x_b + bias   (NN GEMM, M=256, K=256, N=2048)
// 64x64 tile, BK=16, 256 threads, 4x4 microtile.
// blockIdx.z = b*3 + which  (which: 0=q,1=k,2=v)
// ---------------------------------------------------------------------------
__global__ __launch_bounds__(256) void att_qkv_kernel(
    const float* __restrict__ x,
    const float* __restrict__ Wq, const float* __restrict__ bq,
    const float* __restrict__ Wk, const float* __restrict__ bk,
    const float* __restrict__ Wv, const float* __restrict__ bv)
{
    const int bz = blockIdx.z;
    const int b  = bz / 3;
    const int w  = bz - 3 * b;

    const float* W    = (w == 0) ? Wq : ((w == 1) ? Wk : Wv);
    const float* bias = (w == 0) ? bq : ((w == 1) ? bk : bv);
    float* out        = (w == 0) ? g_q : ((w == 1) ? g_k : g_v);

    const float* X = x + (size_t)b * CC * NN;
    out += (size_t)b * CC * NN;

    __shared__ float sA[16][64];   // [k][m]
    __shared__ float sB[16][64];   // [k][n]

    const int tid  = threadIdx.x;
    const int trow = tid >> 4;       // 0..15
    const int tcol = tid & 15;       // 0..15
    const int m0 = blockIdx.y * 64;
    const int n0 = blockIdx.x * 64;

    // A-load: thread loads float4 of W row (m0+am), k-offset ak
    const int am = tid >> 2;            // 0..63
    const int ak = (tid & 3) << 2;      // 0,4,8,12
    // B-load: row kb (0..15), col bn
    const int kb = tid >> 4;            // 0..15
    const int bn = (tid & 15) << 2;     // 0..60

    float acc[4][4] = {};

    for (int k0 = 0; k0 < CC; k0 += 16) {
        float4 av = *reinterpret_cast<const float4*>(&W[(size_t)(m0 + am) * CC + k0 + ak]);
        sA[ak + 0][am] = av.x; sA[ak + 1][am] = av.y;
        sA[ak + 2][am] = av.z; sA[ak + 3][am] = av.w;
        float4 bv4 = *reinterpret_cast<const float4*>(&X[(size_t)(k0 + kb) * NN + n0 + bn]);
        *reinterpret_cast<float4*>(&sB[kb][bn]) = bv4;
        __syncthreads();
#pragma unroll
        for (int kk = 0; kk < 16; kk++) {
            float4 a  = *reinterpret_cast<const float4*>(&sA[kk][trow << 2]);
            float4 bb = *reinterpret_cast<const float4*>(&sB[kk][tcol << 2]);
            float ar[4] = {a.x, a.y, a.z, a.w};
            float br[4] = {bb.x, bb.y, bb.z, bb.w};
#pragma unroll
            for (int i = 0; i < 4; i++)
#pragma unroll
                for (int j = 0; j < 4; j++)
                    acc[i][j] += ar[i] * br[j];
        }
        __syncthreads();
    }

#pragma unroll
    for (int i = 0; i < 4; i++) {
        const int m = m0 + (trow << 2) + i;
        const float bi = bias[m];
        float4 r;
        r.x = acc[i][0] + bi; r.y = acc[i][1] + bi;
        r.z = acc[i][2] + bi; r.w = acc[i][3] + bi;
        *reinterpret_cast<float4*>(&out[(size_t)m * NN + n0 + (tcol << 2)]) = r;
    }
}

// ---------------------------------------------------------------------------
// Kernel 2: per-(b,c) row sums of q and k, product -> g_partial
// ---------------------------------------------------------------------------
__global__ __launch_bounds__(256) void att_rowsum_kernel()
{
    const int idx = blockIdx.x;            // 0 .. B*C-1
    const float* qr = g_q + (size_t)idx * NN;
    const float* kr = g_k + (size_t)idx * NN;
    float sq = 0.f, sk = 0.f;
    for (int n = threadIdx.x; n < NN; n += 256) { sq += qr[n]; sk += kr[n]; }
    __shared__ float rq[256], rk[256];
    rq[threadIdx.x] = sq; rk[threadIdx.x] = sk;
    __syncthreads();
    for (int s = 128; s > 0; s >>= 1) {
        if (threadIdx.x < s) {
            rq[threadIdx.x] += rq[threadIdx.x + s];
            rk[threadIdx.x] += rk[threadIdx.x + s];
        }
        __syncthreads();
    }
    if (threadIdx.x == 0) g_partial[idx] = rq[0] * rk[0];
}

// ---------------------------------------------------------------------------
// Kernel 3: S = sum(partials) (double accum, deterministic tree), g_inv = 1/S
// ---------------------------------------------------------------------------
__global__ __launch_bounds__(256) void att_reduce_s_kernel()
{
    __shared__ double sd[256];
    double s = 0.0;
    for (int i = threadIdx.x; i < BB * CC; i += 256) s += (double)g_partial[i];
    sd[threadIdx.x] = s;
    __syncthreads();
    for (int st = 128; st > 0; st >>= 1) {
        if (threadIdx.x < st) sd[threadIdx.x] += sd[threadIdx.x + st];
        __syncthreads();
    }
    if (threadIdx.x == 0) g_inv = (float)(1.0 / sd[0]);
}

// ---------------------------------------------------------------------------
// Kernel 4: M[b] = V_b @ Q_b^T   (NT GEMM, M=N=256, K=2048)
// ---------------------------------------------------------------------------
__global__ __launch_bounds__(256) void att_vq_kernel()
{
    const int b = blockIdx.z;
    const float* V = g_v + (size_t)b * CC * NN;
    const float* Q = g_q + (size_t)b * CC * NN;
    float* M = g_M + (size_t)b * CC * CC;

    __shared__ float sA[16][64];   // [k][c1]
    __shared__ float sB[16][64];   // [k][c2]

    const int tid  = threadIdx.x;
    const int trow = tid >> 4;
    const int tcol = tid & 15;
    const int m0 = blockIdx.y * 64;
    const int n0 = blockIdx.x * 64;

    const int am = tid >> 2;
    const int ak = (tid & 3) << 2;

    float acc[4][4] = {};

    for (int k0 = 0; k0 < NN; k0 += 16) {
        float4 av = *reinterpret_cast<const float4*>(&V[(size_t)(m0 + am) * NN + k0 + ak]);
        sA[ak + 0][am] = av.x; sA[ak + 1][am] = av.y;
        sA[ak + 2][am] = av.z; sA[ak + 3][am] = av.w;
        float4 bv4 = *reinterpret_cast<const float4*>(&Q[(size_t)(n0 + am) * NN + k0 + ak]);
        sB[ak + 0][am] = bv4.x; sB[ak + 1][am] = bv4.y;
        sB[ak + 2][am] = bv4.z; sB[ak + 3][am] = bv4.w;
        __syncthreads();
#pragma unroll
        for (int kk = 0; kk < 16; kk++) {
            float4 a  = *reinterpret_cast<const float4*>(&sA[kk][trow << 2]);
            float4 bb = *reinterpret_cast<const float4*>(&sB[kk][tcol << 2]);
            float ar[4] = {a.x, a.y, a.z, a.w};
            float br[4] = {bb.x, bb.y, bb.z, bb.w};
#pragma unroll
            for (int i = 0; i < 4; i++)
#pragma unroll
                for (int j = 0; j < 4; j++)
                    acc[i][j] += ar[i] * br[j];
        }
        __syncthreads();
    }

#pragma unroll
    for (int i = 0; i < 4; i++) {
        const int m = m0 + (trow << 2) + i;
        float4 r;
        r.x = acc[i][0]; r.y = acc[i][1]; r.z = acc[i][2]; r.w = acc[i][3];
        *reinterpret_cast<float4*>(&M[(size_t)m * CC + n0 + (tcol << 2)]) = r;
    }
}

// ---------------------------------------------------------------------------
// Kernel 5: out[b] = (M[b] @ K_b) * (1/S)   (NN GEMM, M=256, K=256, N=2048)
// ---------------------------------------------------------------------------
__global__ __launch_bounds__(256) void att_out_kernel(float* __restrict__ outp)
{
    const int b = blockIdx.z;
    const float* A  = g_M + (size_t)b * CC * CC;
    const float* Bk = g_k + (size_t)b * CC * NN;
    float* O = outp + (size_t)b * CC * NN;
    const float inv = g_inv;

    __shared__ float sA[16][64];
    __shared__ float sB[16][64];

    const int tid  = threadIdx.x;
    const int trow = tid >> 4;
    const int tcol = tid & 15;
    const int m0 = blockIdx.y * 64;
    const int n0 = blockIdx.x * 64;

    const int am = tid >> 2;
    const int ak = (tid & 3) << 2;
    const int kb = tid >> 4;
    const int bn = (tid & 15) << 2;

    float acc[4][4] = {};

    for (int k0 = 0; k0 < CC; k0 += 16) {
        float4 av = *reinterpret_cast<const float4*>(&A[(size_t)(m0 + am) * CC + k0 + ak]);
        sA[ak + 0][am] = av.x; sA[ak + 1][am] = av.y;
        sA[ak + 2][am] = av.z; sA[ak + 3][am] = av.w;
        float4 bv4 = *reinterpret_cast<const float4*>(&Bk[(size_t)(k0 + kb) * NN + n0 + bn]);
        *reinterpret_cast<float4*>(&sB[kb][bn]) = bv4;
        __syncthreads();
#pragma unroll
        for (int kk = 0; kk < 16; kk++) {
            float4 a  = *reinterpret_cast<const float4*>(&sA[kk][trow << 2]);
            float4 bb = *reinterpret_cast<const float4*>(&sB[kk][tcol << 2]);
            float ar[4] = {a.x, a.y, a.z, a.w};
            float br[4] = {bb.x, bb.y, bb.z, bb.w};
#pragma unroll
            for (int i = 0; i < 4; i++)
#pragma unroll
                for (int j = 0; j < 4; j++)
                    acc[i][j] += ar[i] * br[j];
        }
        __syncthreads();
    }

#pragma unroll
    for (int i = 0; i < 4; i++) {
        const int m = m0 + (trow << 2) + i;
        float4 r;
        r.x = acc[i][0] * inv; r.y = acc[i][1] * inv;
        r.z = acc[i][2] * inv; r.w = acc[i][3] * inv;
        *reinterpret_cast<float4*>(&O[(size_t)m * NN + n0 + (tcol << 2)]) = r;
    }
}

// ---------------------------------------------------------------------------
// Launch
// ---------------------------------------------------------------------------
extern "C" void kernel_launch(void* const* d_in, const int* in_sizes, int n_in,
                              void* d_out, int out_size)
{
    const float* x  = (const float*)d_in[0];
    const float* Wq = (const float*)d_in[1];
    const float* bq = (const float*)d_in[2];
    const float* Wk = (const float*)d_in[3];
    const float* bk = (const float*)d_in[4];
    const float* Wv = (const float*)d_in[5];
    const float* bv = (const float*)d_in[6];
    float* out = (float*)d_out;

    // 1) q,k,v projections: grid (N/64, C/64, B*3)
    dim3 g1(NN / 64, CC / 64, BB * 3);
    att_qkv_kernel<<<g1, 256>>>(x, Wq, bq, Wk, bk, Wv, bv);

    // 2) row sums -> partials
    att_rowsum_kernel<<<BB * CC, 256>>>();

    // 3) S reduction -> 1/S
    att_reduce_s_kernel<<<1, 256>>>();

    // 4) M[b] = V Q^T : grid (C/64, C/64, B)
    dim3 g2(CC / 64, CC / 64, BB);
    att_vq_kernel<<<g2, 256>>>();

    // 5) out = M K / S : grid (N/64, C/64, B)
    dim3 g3(NN / 64, CC / 64, BB);
    att_out_kernel<<<g3, 256>>>(out);
}

// round 3
// speedup vs baseline: 1.2105x; 1.2105x over previous
#include <cuda_runtime.h>
#include <cuda_bf16.h>

#define BB 8
#define CC 256
#define NN 2048

typedef __nv_bfloat16 bf16;

// ---------------- scratch (device globals; no allocs allowed) ----------------
__device__ bf16  g_xs [BB * NN * 2 * CC];   // x  split, [b][n][hi c | lo c]
__device__ bf16  g_Ws [3 * CC * 2 * CC];    // W  split, [m(768)][hi c | lo c]
__device__ float g_bias[3 * CC];
__device__ bf16  g_qs [BB * CC * 2 * NN];   // q  split, [b*C+c][hi n | lo n]
__device__ bf16  g_vs [BB * CC * 2 * NN];   // v  split
__device__ float g_kf [BB * CC * NN];       // k  fp32   [b][c][n]
__device__ bf16  g_ksT[BB * NN * 2 * CC];   // k  split transposed [b][n][hi c | lo c]
__device__ float g_Mpart[8 * BB * CC * CC]; // split-K partials [chunk][b][c1][c2]
__device__ bf16  g_Ms [BB * CC * 2 * CC];   // M  split, [b*C+c1][hi c2 | lo c2]
__device__ float g_partial[BB * CC];
__device__ float g_inv;

// ---------------- helpers ----------------
__device__ __forceinline__ void split_store(bf16* row, int n, int lo_off,
                                            float v0, float v1)
{
    __nv_bfloat162 h, l;
    h.x = __float2bfloat16(v0);
    h.y = __float2bfloat16(v1);
    l.x = __float2bfloat16(v0 - __bfloat162float(h.x));
    l.y = __float2bfloat16(v1 - __bfloat162float(h.y));
    *reinterpret_cast<__nv_bfloat162*>(row + n)          = h;
    *reinterpret_cast<__nv_bfloat162*>(row + lo_off + n) = l;
}

__device__ __forceinline__ void mma16816(float* c, const unsigned* a, const unsigned* b)
{
    asm volatile(
        "mma.sync.aligned.m16n8k16.row.col.f32.bf16.bf16.f32 "
        "{%0,%1,%2,%3},{%4,%5,%6,%7},{%8,%9},{%0,%1,%2,%3};\n"
        : "+f"(c[0]), "+f"(c[1]), "+f"(c[2]), "+f"(c[3])
        : "r"(a[0]), "r"(a[1]), "r"(a[2]), "r"(a[3]), "r"(b[0]), "r"(b[1]));
}

// map logical k'' in [0,3K) onto [hi|lo] columns of split operands:
// term 0: A hi, B hi ; term 1: A hi, B lo ; term 2: A lo, B hi
__device__ __forceinline__ void koffs(int kk, int K, int& ka, int& kb)
{
    int term = kk / K;
    int kmod = kk - term * K;
    ka = (term == 2 ? K : 0) + kmod;
    kb = (term == 1 ? K : 0) + kmod;
}

// ---------------- the shared GEMM (TN, bf16 split, 128x128x32 tiles) --------
// EPI 0: qkv projections   A=Ws[768,2C]           B=xs[b][2048,2C]   K=256
// EPI 1: M partial (splitK) A=vs[b][256,2N]        B=qs[b][256,2N]    K=2048
// EPI 2: out = M*k/S       A=Ms[b][256,2C]        B=ksT[b][2048,2C]  K=256
template <int EPI>
__global__ __launch_bounds__(256) void gemm_bf16_kernel(float* __restrict__ dout)
{
    __shared__ unsigned sA[2][128 * 20];   // padded rows: 20 words (16 data + 4 pad)
    __shared__ unsigned sB[2][128 * 20];

    const int tid  = threadIdx.x;
    const int lane = tid & 31;
    const int w    = tid >> 5;
    const int wm   = w >> 2;           // 0..1
    const int wn   = w & 3;            // 0..3
    const int g    = lane >> 2;        // 0..7
    const int t    = lane & 3;         // 0..3
    const int m0   = blockIdx.y * 128;
    const int n0   = blockIdx.x * 128;

    const bf16 *A, *Bm;
    int ldA, ldB, K, kk0, kk1, b, ch = 0;
    if (EPI == 0) {
        b = blockIdx.z;
        A = g_Ws;                        ldA = 2 * CC;
        Bm = g_xs + (size_t)b * NN * 2 * CC; ldB = 2 * CC;
        K = CC; kk0 = 0; kk1 = 3 * CC;
    } else if (EPI == 1) {
        int z = blockIdx.z; b = z >> 3; ch = z & 7;
        A  = g_vs + (size_t)b * CC * 2 * NN;
        Bm = g_qs + (size_t)b * CC * 2 * NN;
        ldA = ldB = 2 * NN; K = NN;
        kk0 = ch * 768; kk1 = kk0 + 768;
    } else {
        b = blockIdx.z;
        A  = g_Ms  + (size_t)b * CC * 2 * CC; ldA = 2 * CC;
        Bm = g_ksT + (size_t)b * NN * 2 * CC; ldB = 2 * CC;
        K = CC; kk0 = 0; kk1 = 3 * CC;
    }

    float acc[4][4][4];
#pragma unroll
    for (int i = 0; i < 4; i++)
#pragma unroll
        for (int j = 0; j < 4; j++)
#pragma unroll
            for (int q = 0; q < 4; q++) acc[i][j][q] = 0.f;

    const int rA = tid >> 2;           // tile row 0..63 (and +64)
    const int cw = (tid & 3) * 4;      // word col for STS
    const int ce = (tid & 3) * 8;      // element col for LDG (16B)

    // prologue: fill buffer 0
    {
        int ka, kb; koffs(kk0, K, ka, kb);
        const bf16* pa = A  + (size_t)(m0 + rA) * ldA + ka + ce;
        const bf16* pb = Bm + (size_t)(n0 + rA) * ldB + kb + ce;
        uint4 a0 = *(const uint4*)pa, a1 = *(const uint4*)(pa + (size_t)64 * ldA);
        uint4 b0 = *(const uint4*)pb, b1 = *(const uint4*)(pb + (size_t)64 * ldB);
        *(uint4*)&sA[0][rA * 20 + cw]        = a0;
        *(uint4*)&sA[0][(rA + 64) * 20 + cw] = a1;
        *(uint4*)&sB[0][rA * 20 + cw]        = b0;
        *(uint4*)&sB[0][(rA + 64) * 20 + cw] = b1;
    }
    __syncthreads();

    int buf = 0;
    for (int kk = kk0; kk < kk1; kk += 32) {
        const bool hasNext = (kk + 32) < kk1;
        uint4 na0, na1, nb0, nb1;
        if (hasNext) {
            int ka, kb; koffs(kk + 32, K, ka, kb);
            const bf16* pa = A  + (size_t)(m0 + rA) * ldA + ka + ce;
            const bf16* pb = Bm + (size_t)(n0 + rA) * ldB + kb + ce;
            na0 = *(const uint4*)pa; na1 = *(const uint4*)(pa + (size_t)64 * ldA);
            nb0 = *(const uint4*)pb; nb1 = *(const uint4*)(pb + (size_t)64 * ldB);
        }
        const unsigned* sa = sA[buf];
        const unsigned* sb = sB[buf];
#pragma unroll
        for (int s = 0; s < 2; s++) {
            const int so = s * 8 + t;
            unsigned af[4][4];
#pragma unroll
            for (int mt = 0; mt < 4; mt++) {
                int r = (wm * 64 + mt * 16 + g) * 20 + so;
                af[mt][0] = sa[r];       af[mt][1] = sa[r + 160];
                af[mt][2] = sa[r + 4];   af[mt][3] = sa[r + 164];
            }
            unsigned bfr[4][2];
#pragma unroll
            for (int nt = 0; nt < 4; nt++) {
                int r = (wn * 32 + nt * 8 + g) * 20 + so;
                bfr[nt][0] = sb[r]; bfr[nt][1] = sb[r + 4];
            }
#pragma unroll
            for (int mt = 0; mt < 4; mt++)
#pragma unroll
                for (int nt = 0; nt < 4; nt++)
                    mma16816(acc[mt][nt], af[mt], bfr[nt]);
        }
        if (hasNext) {
            int nb = buf ^ 1;
            *(uint4*)&sA[nb][rA * 20 + cw]        = na0;
            *(uint4*)&sA[nb][(rA + 64) * 20 + cw] = na1;
            *(uint4*)&sB[nb][rA * 20 + cw]        = nb0;
            *(uint4*)&sB[nb][(rA + 64) * 20 + cw] = nb1;
            __syncthreads();
            buf = nb;
        }
    }

    // epilogue
#pragma unroll
    for (int mt = 0; mt < 4; mt++) {
#pragma unroll
        for (int nt = 0; nt < 4; nt++) {
            float* ac = acc[mt][nt];
            const int m = m0 + wm * 64 + mt * 16 + g;
            const int n = n0 + wn * 32 + nt * 8 + 2 * t;
#pragma unroll
            for (int h = 0; h < 2; h++) {
                const int mr = m + h * 8;
                float v0 = ac[2 * h + 0], v1 = ac[2 * h + 1];
                if (EPI == 0) {
                    const float bia = g_bias[mr];
                    v0 += bia; v1 += bia;
                    const int proj = mr >> 8;       // uniform per CTA
                    const int ml   = mr & 255;
                    if (proj == 0) {
                        split_store(g_qs + (size_t)(b * CC + ml) * 2 * NN, n, NN, v0, v1);
                    } else if (proj == 1) {
                        float2 f = make_float2(v0, v1);
                        *(float2*)&g_kf[(size_t)(b * CC + ml) * NN + n] = f;
                    } else {
                        split_store(g_vs + (size_t)(b * CC + ml) * 2 * NN, n, NN, v0, v1);
                    }
                } else if (EPI == 1) {
                    float2 f = make_float2(v0, v1);
                    *(float2*)&g_Mpart[(size_t)((ch * BB + b) * CC + mr) * CC + n] = f;
                } else {
                    const float inv = g_inv;
                    float2 f = make_float2(v0 * inv, v1 * inv);
                    *(float2*)&dout[(size_t)(b * CC + mr) * NN + n] = f;
                }
            }
        }
    }
}

// ---------------- transpose + split: [b][C][N] f32 -> [b][N][hi C|lo C] bf16 --
// MODE 0: src = x (kernel arg), dst = g_xs ; MODE 1: src = g_kf, dst = g_ksT
template <int MODE>
__global__ void transpose_split_kernel(const float* __restrict__ xsrc)
{
    __shared__ float tile[32][33];
    const int b  = blockIdx.z;
    const int c0 = blockIdx.y * 32;
    const int n0 = blockIdx.x * 32;
    const float* S = (MODE == 0 ? xsrc : g_kf) + (size_t)b * CC * NN;
    bf16* D = (MODE == 0 ? g_xs : g_ksT) + (size_t)b * NN * 2 * CC;

#pragma unroll
    for (int i = 0; i < 4; i++)
        tile[threadIdx.y + i * 8][threadIdx.x] =
            S[(size_t)(c0 + threadIdx.y + i * 8) * NN + n0 + threadIdx.x];
    __syncthreads();
#pragma unroll
    for (int i = 0; i < 4; i++) {
        const int n = n0 + threadIdx.y + i * 8;
        const int c = c0 + threadIdx.x;
        const float v = tile[threadIdx.x][threadIdx.y + i * 8];
        const bf16 hi = __float2bfloat16(v);
        D[(size_t)n * 2 * CC + c]      = hi;
        D[(size_t)n * 2 * CC + CC + c] = __float2bfloat16(v - __bfloat162float(hi));
    }
}

// ---------------- W / bias prep ----------------
__global__ void wprep_kernel(const float* __restrict__ Wq, const float* __restrict__ bq,
                             const float* __restrict__ Wk, const float* __restrict__ bk,
                             const float* __restrict__ Wv, const float* __restrict__ bv)
{
    const int m = blockIdx.x;       // 0..767
    const int c = threadIdx.x;      // 0..255
    const float* Wsrc = (m < CC) ? Wq : (m < 2 * CC) ? Wk : Wv;
    const int ml = m & (CC - 1);
    const float v = Wsrc[ml * CC + c];
    const bf16 hi = __float2bfloat16(v);
    g_Ws[(size_t)m * 2 * CC + c]      = hi;
    g_Ws[(size_t)m * 2 * CC + CC + c] = __float2bfloat16(v - __bfloat162float(hi));
    if (c == 0) g_bias[m] = (m < CC) ? bq[ml] : (m < 2 * CC) ? bk[ml] : bv[ml];
}

// ---------------- row sums (q from split, k from fp32) ----------------
__global__ __launch_bounds__(256) void rowsum_kernel()
{
    const int idx = blockIdx.x;                 // b*C + c
    const bf16*  q = g_qs + (size_t)idx * 2 * NN;
    const float* k = g_kf + (size_t)idx * NN;
    float sq = 0.f, sk = 0.f;
    for (int n = threadIdx.x; n < NN; n += 256) {
        sq += __bfloat162float(q[n]) + __bfloat162float(q[NN + n]);
        sk += k[n];
    }
    __shared__ float rq[256], rk[256];
    rq[threadIdx.x] = sq; rk[threadIdx.x] = sk;
    __syncthreads();
    for (int s = 128; s > 0; s >>= 1) {
        if (threadIdx.x < s) {
            rq[threadIdx.x] += rq[threadIdx.x + s];
            rk[threadIdx.x] += rk[threadIdx.x + s];
        }
        __syncthreads();
    }
    if (threadIdx.x == 0) g_partial[idx] = rq[0] * rk[0];
}

__global__ __launch_bounds__(256) void sreduce_kernel()
{
    __shared__ double sd[256];
    double s = 0.0;
    for (int i = threadIdx.x; i < BB * CC; i += 256) s += (double)g_partial[i];
    sd[threadIdx.x] = s;
    __syncthreads();
    for (int st = 128; st > 0; st >>= 1) {
        if (threadIdx.x < st) sd[threadIdx.x] += sd[threadIdx.x + st];
        __syncthreads();
    }
    if (threadIdx.x == 0) g_inv = (float)(1.0 / sd[0]);
}

// ---------------- split-K reduce for M + bf16 split ----------------
__global__ __launch_bounds__(256) void mreduce_kernel()
{
    const int b  = blockIdx.x >> 8;
    const int c1 = blockIdx.x & 255;
    const int c2 = threadIdx.x;
    float s = 0.f;
#pragma unroll
    for (int chn = 0; chn < 8; chn++)
        s += g_Mpart[(size_t)((chn * BB + b) * CC + c1) * CC + c2];
    const bf16 hi = __float2bfloat16(s);
    g_Ms[(size_t)(b * CC + c1) * 2 * CC + c2]      = hi;
    g_Ms[(size_t)(b * CC + c1) * 2 * CC + CC + c2] = __float2bfloat16(s - __bfloat162float(hi));
}

// ---------------- launch ----------------
extern "C" void kernel_launch(void* const* d_in, const int* in_sizes, int n_in,
                              void* d_out, int out_size)
{
    const float* x  = (const float*)d_in[0];
    const float* Wq = (const float*)d_in[1];
    const float* bq = (const float*)d_in[2];
    const float* Wk = (const float*)d_in[3];
    const float* bk = (const float*)d_in[4];
    const float* Wv = (const float*)d_in[5];
    const float* bv = (const float*)d_in[6];
    float* out = (float*)d_out;

    dim3 tb(32, 8);
    // 0) operand prep
    transpose_split_kernel<0><<<dim3(NN / 32, CC / 32, BB), tb>>>(x);
    wprep_kernel<<<3 * CC, 256>>>(Wq, bq, Wk, bk, Wv, bv);
    // 1) fused qkv projections (M=768, N=2048, K=256) per batch
    gemm_bf16_kernel<0><<<dim3(NN / 128, (3 * CC) / 128, BB), 256>>>(nullptr);
    // 2) S = sum(qk) via factored row sums
    rowsum_kernel<<<BB * CC, 256>>>();
    sreduce_kernel<<<1, 256>>>();
    // 3) k transpose+split for the final GEMM
    transpose_split_kernel<1><<<dim3(NN / 32, CC / 32, BB), tb>>>(nullptr);
    // 4) M[b] = V Q^T with split-K x8 (grid 2x2x64)
    gemm_bf16_kernel<1><<<dim3(CC / 128, CC / 128, BB * 8), 256>>>(nullptr);
    // 5) reduce partials + split M
    mreduce_kernel<<<BB * CC, 256>>>();
    // 6) out = (M K) / S
    gemm_bf16_kernel<2><<<dim3(NN / 128, CC / 128, BB), 256>>>(out);
}